// round 7
// baseline (speedup 1.0000x reference)
#include <cuda_runtime.h>

// Problem constants (from reference)
#define BB 16
#define AA 128
#define PP 8192
#define TT 5
#define K_LOG2E 1.4426950408889634f   // log2(e); TEMPERATURE = 1.0
#define LN2F    0.6931471805599453f   // 1/log2(e)
#define CLIP    0.3f

#define THREADS 256          // 8 warps/block
#define QPB 128              // queries per block: 2 threads cooperate per query
#define MAXA 160             // 128 atoms + up to 5*3 pad, rounded up

typedef unsigned long long ull;

__device__ __forceinline__ float ex2f_a(float x) {
    float y; asm("ex2.approx.ftz.f32 %0, %1;" : "=f"(y) : "f"(x)); return y;
}
__device__ __forceinline__ float sqrtf_a(float x) {
    float y; asm("sqrt.approx.ftz.f32 %0, %1;" : "=f"(y) : "f"(x)); return y;
}
__device__ __forceinline__ float rcpf_a(float x) {
    float y; asm("rcp.approx.ftz.f32 %0, %1;" : "=f"(y) : "f"(x)); return y;
}
__device__ __forceinline__ float rsqrtf_a(float x) {
    float y; asm("rsqrt.approx.ftz.f32 %0, %1;" : "=f"(y) : "f"(x)); return y;
}

__device__ __forceinline__ ull f2_pack(float lo, float hi) {
    ull r; asm("mov.b64 %0, {%1, %2};" : "=l"(r) : "f"(lo), "f"(hi)); return r;
}
__device__ __forceinline__ void f2_unpack(float& lo, float& hi, ull v) {
    asm("mov.b64 {%0, %1}, %2;" : "=f"(lo), "=f"(hi) : "l"(v));
}
__device__ __forceinline__ ull f2_fma(ull a, ull b, ull c) {
    ull d; asm("fma.rn.f32x2 %0, %1, %2, %3;" : "=l"(d) : "l"(a), "l"(b), "l"(c)); return d;
}

__global__ void __launch_bounds__(THREADS, 8)
gnf_kernel(const float* __restrict__ coords,     // [B, A, 3] f32
           const int*   __restrict__ types_raw,  // [B, A] int32 OR int64 (detected)
           const float* __restrict__ query,      // [B, P, 3] f32
           float*       __restrict__ out)        // [B, P, T, 3] f32
{
    // dual storage per sorted atom:
    //   sC[i] = (cx', cy', cz', |c'|^2)   (scaled by log2e)  -> d^2 dot chain
    //   sP[i] = { pack(1, cx'), pack(cy', cz') }             -> packed accumulate
    __shared__ float4 sC[MAXA];
    __shared__ ulonglong2 sP[MAXA];
    __shared__ int sStart[TT + 1];
    __shared__ int sCnt[TT];
    __shared__ int sOffs[TT];

    const int tid = threadIdx.x;
    const int b   = blockIdx.y;

    // ---- sentinel: |c'|^2=1e30 -> w = ex2(-1e15) == 0; packed coords 0 -> no contrib
    for (int j = tid; j < MAXA; j += THREADS) {
        sC[j] = make_float4(0.f, 0.f, 0.f, 1e30f);
        sP[j].x = f2_pack(1.f, 0.f);
        sP[j].y = 0ULL;
    }
    if (tid < TT) sCnt[tid] = 0;

    // ---- dtype detection: sample first 512 words' odd positions (one LDG/thread).
    // int64 iff all sampled odd words in {0,-1}; int32 types 0..4 hit >0 w.p. 1-(1/5)^256
    {
        int w = types_raw[2 * (tid & 255) + 1];
        bool okk = (w == 0) || (w == -1);
        // reuse below via ballot through syncthreads_and
        const int is64_ = __syncthreads_and(okk ? 1 : 0);
        // stash in shared? cheaper: recompute path below with is64_ captured
        // (fall through with is64_ in a register)
        // ---- counting sort of this batch's 128 atoms by type, segments padded to x4
        int t_mine = -1;
        if (tid < AA) {
            long long tv;
            if (is64_) tv = ((const long long*)types_raw)[(long)b * AA + tid];
            else       tv = (long long)types_raw[(long)b * AA + tid];
            if (tv >= 0 && tv < TT) {
                t_mine = (int)tv;
                atomicAdd(&sCnt[t_mine], 1);
            }
        }
        __syncthreads();
        if (tid == 0) {
            int s = 0;
            #pragma unroll
            for (int k = 0; k < TT; k++) {
                sStart[k] = s; sOffs[k] = s;
                s += (sCnt[k] + 3) & ~3;     // pad each segment to multiple of 4
            }
            sStart[TT] = s;
        }
        __syncthreads();
        if (t_mine >= 0) {
            int pos = atomicAdd(&sOffs[t_mine], 1);
            const float* c = coords + ((long)b * AA + tid) * 3;
            float cx = c[0] * K_LOG2E, cy = c[1] * K_LOG2E, cz = c[2] * K_LOG2E;
            sC[pos] = make_float4(cx, cy, cz, fmaf(cx, cx, fmaf(cy, cy, cz * cz)));
            sP[pos].x = f2_pack(1.f, cx);
            sP[pos].y = f2_pack(cy, cz);
        }
        __syncthreads();
    }

    // ---- 2 threads per query: lanes l and l^16 share a query; h = atom half
    const int warp = tid >> 5;
    const int lane = tid & 31;
    const int h    = lane >> 4;
    const int q0   = blockIdx.x * QPB + warp * 16 + (lane & 15);

    const float* qp = query + ((long)b * PP + q0) * 3;
    const float qox = qp[0], qoy = qp[1], qoz = qp[2];
    const float nx = qox * (-2.f * K_LOG2E);   // -2*q'
    const float ny = qoy * (-2.f * K_LOG2E);
    const float nz = qoz * (-2.f * K_LOG2E);
    const float qq2 = 0.25f * fmaf(nx, nx, fmaf(ny, ny, nz * nz));   // +|q'|^2

    float* outp = out + ((long)b * PP + q0) * (TT * 3);

    #pragma unroll
    for (int t = 0; t < TT; t++) {
        const int s = sStart[t], e = sStart[t + 1];   // length multiple of 4
        ull SG0 = 0ULL, YZ0 = 0ULL;     // (S, Gx), (Gy, Gz) stream 0
        ull SG1 = 0ULL, YZ1 = 0ULL;     // stream 1

        // my half: atoms s+h, s+h+2, ...; unroll-2 -> two sqrt->ex2 chains in flight
        for (int i = s + h; i < e; i += 4) {
            const float4 c0 = sC[i];
            const float4 c1 = sC[i + 2];
            const ulonglong2 p0 = sP[i];
            const ulonglong2 p1 = sP[i + 2];

            // d2 = |c|^2 + |q|^2 - 2 c.q
            float d20 = fmaf(c0.x, nx, fmaf(c0.y, ny, fmaf(c0.z, nz, c0.w))) + qq2;
            float d21 = fmaf(c1.x, nx, fmaf(c1.y, ny, fmaf(c1.z, nz, c1.w))) + qq2;

            float w0 = ex2f_a(-sqrtf_a(d20));
            float w1 = ex2f_a(-sqrtf_a(d21));

            const ull wp0 = f2_pack(w0, w0);
            const ull wp1 = f2_pack(w1, w1);

            SG0 = f2_fma(wp0, p0.x, SG0);   // (S += w, Gx += w*cx)
            YZ0 = f2_fma(wp0, p0.y, YZ0);   // (Gy += w*cy, Gz += w*cz)
            SG1 = f2_fma(wp1, p1.x, SG1);
            YZ1 = f2_fma(wp1, p1.y, YZ1);
        }

        float Sa, Gxa, Sb, Gxb, Gya, Gza, Gyb, Gzb;
        f2_unpack(Sa, Gxa, SG0);
        f2_unpack(Sb, Gxb, SG1);
        f2_unpack(Gya, Gza, YZ0);
        f2_unpack(Gyb, Gzb, YZ1);
        float S = Sa + Sb, Gx = Gxa + Gxb, Gy = Gya + Gyb, Gz = Gza + Gzb;

        // combine the two atom-halves (partner lane l^16 holds the other half)
        S  += __shfl_xor_sync(0xffffffffu, S, 16);
        Gx += __shfl_xor_sync(0xffffffffu, Gx, 16);
        Gy += __shfl_xor_sync(0xffffffffu, Gy, 16);
        Gz += __shfl_xor_sync(0xffffffffu, Gz, 16);

        // finalize: grad = (Gc/S)/L - q_orig; clip to 0.3; empty type -> 0
        if ((t & 1) == h) {
            float gx = 0.f, gy = 0.f, gz = 0.f;
            if (S > 0.f) {
                float inv = rcpf_a(S) * LN2F;
                gx = fmaf(Gx, inv, -qox);
                gy = fmaf(Gy, inv, -qoy);
                gz = fmaf(Gz, inv, -qoz);
                float m2 = fmaf(gx, gx, fmaf(gy, gy, gz * gz));
                if (m2 > CLIP * CLIP) {
                    float sc = CLIP * rsqrtf_a(m2);
                    gx *= sc; gy *= sc; gz *= sc;
                }
            }
            outp[t * 3 + 0] = gx; outp[t * 3 + 1] = gy; outp[t * 3 + 2] = gz;
        }
    }
}

extern "C" void kernel_launch(void* const* d_in, const int* in_sizes, int n_in,
                              void* d_out, int out_size)
{
    const float* coords = (const float*)d_in[0];   // [16,128,3] f32
    const int*   types  = (const int*)d_in[1];     // [16,128] int32/int64 (detected on device)
    const float* query  = (const float*)d_in[2];   // [16,8192,3] f32
    float*       out    = (float*)d_out;           // [16,8192,5,3] f32

    dim3 grid(PP / QPB, BB);   // (64, 16) = 1024 blocks x 256 threads
    gnf_kernel<<<grid, THREADS>>>(coords, types, query, out);
}

// round 8
// speedup vs baseline: 1.0033x; 1.0033x over previous
#include <cuda_runtime.h>

// Problem constants (from reference)
#define BB 16
#define AA 128
#define PP 8192
#define TT 5
#define K_LOG2E 1.4426950408889634f   // log2(e); TEMPERATURE = 1.0
#define LN2F    0.6931471805599453f   // 1/log2(e)
#define CLIP    0.3f

#define THREADS 256          // 8 warps/block, 1 query per thread
#define MAXA 160             // 128 atoms + up to 5*3 pad, rounded up

__device__ __forceinline__ float ex2f_a(float x) {
    float y; asm("ex2.approx.ftz.f32 %0, %1;" : "=f"(y) : "f"(x)); return y;
}
__device__ __forceinline__ float sqrtf_a(float x) {
    float y; asm("sqrt.approx.ftz.f32 %0, %1;" : "=f"(y) : "f"(x)); return y;
}
__device__ __forceinline__ float rcpf_a(float x) {
    float y; asm("rcp.approx.ftz.f32 %0, %1;" : "=f"(y) : "f"(x)); return y;
}
__device__ __forceinline__ float rsqrtf_a(float x) {
    float y; asm("rsqrt.approx.ftz.f32 %0, %1;" : "=f"(y) : "f"(x)); return y;
}

__global__ void __launch_bounds__(THREADS)
gnf_kernel(const float* __restrict__ coords,     // [B, A, 3] f32
           const int*   __restrict__ types_raw,  // [B, A] int32 OR int64 (detected)
           const float* __restrict__ query,      // [B, P, 3] f32
           float*       __restrict__ out)        // [B, P, T, 3] f32
{
    // satoms[i] = (cx', cy', cz', |c'|^2), c' = c * log2(e)
    __shared__ float4 satoms[MAXA];
    __shared__ int sStart[TT + 1];   // padded starts, multiples of 4
    __shared__ int sCnt[TT];
    __shared__ int sOffs[TT];

    const int tid = threadIdx.x;
    const int b   = blockIdx.y;

    // ---- sentinel: |c'|^2 = 1e30 -> w = ex2(-1e15) == 0 exactly; coords 0
    for (int j = tid; j < MAXA; j += THREADS)
        satoms[j] = make_float4(0.f, 0.f, 0.f, 1e30f);
    if (tid < TT) sCnt[tid] = 0;

    // ---- dtype detection: sample odd words 1..511 (1 LDG/thread); int64 iff all in {0,-1}
    {
        int w = types_raw[2 * (tid & 255) + 1];
        bool okk = (w == 0) || (w == -1);
        const int is64 = __syncthreads_and(okk ? 1 : 0);   // also fences sentinel fill

        // ---- counting sort of this batch's 128 atoms by type, segments padded to x4
        int t_mine = -1;
        if (tid < AA) {
            long long tv;
            if (is64) tv = ((const long long*)types_raw)[(long)b * AA + tid];
            else      tv = (long long)types_raw[(long)b * AA + tid];
            if (tv >= 0 && tv < TT) {
                t_mine = (int)tv;
                atomicAdd(&sCnt[t_mine], 1);
            }
        }
        __syncthreads();
        if (tid == 0) {
            int s = 0;
            #pragma unroll
            for (int k = 0; k < TT; k++) {
                sStart[k] = s; sOffs[k] = s;
                s += (sCnt[k] + 3) & ~3;
            }
            sStart[TT] = s;
        }
        __syncthreads();
        if (t_mine >= 0) {
            int pos = atomicAdd(&sOffs[t_mine], 1);
            const float* c = coords + ((long)b * AA + tid) * 3;
            float cx = c[0] * K_LOG2E, cy = c[1] * K_LOG2E, cz = c[2] * K_LOG2E;
            satoms[pos] = make_float4(cx, cy, cz, fmaf(cx, cx, fmaf(cy, cy, cz * cz)));
        }
        __syncthreads();
    }

    // ---- one query per thread
    const int q0 = blockIdx.x * THREADS + tid;
    const float* qp = query + ((long)b * PP + q0) * 3;
    const float qox = qp[0], qoy = qp[1], qoz = qp[2];
    const float nx = qox * (-2.f * K_LOG2E);   // -2*q'
    const float ny = qoy * (-2.f * K_LOG2E);
    const float nz = qoz * (-2.f * K_LOG2E);
    const float qq2 = 0.25f * fmaf(nx, nx, fmaf(ny, ny, nz * nz));   // +|q'|^2

    float* outp = out + ((long)b * PP + q0) * (TT * 3);

    #pragma unroll
    for (int t = 0; t < TT; t++) {
        const int s = sStart[t], e = sStart[t + 1];   // length multiple of 4

        float S0 = 0.f, X0 = 0.f, Y0 = 0.f, Z0 = 0.f;
        float S1 = 0.f, X1 = 0.f, Y1 = 0.f, Z1 = 0.f;
        float S2 = 0.f, X2 = 0.f, Y2 = 0.f, Z2 = 0.f;
        float S3 = 0.f, X3 = 0.f, Y3 = 0.f, Z3 = 0.f;

        // 4 independent LDS -> d2 -> sqrt -> ex2 -> accum chains per iteration
        for (int i = s; i < e; i += 4) {
            const float4 c0 = satoms[i];
            const float4 c1 = satoms[i + 1];
            const float4 c2 = satoms[i + 2];
            const float4 c3 = satoms[i + 3];

            float d0 = fmaf(c0.x, nx, fmaf(c0.y, ny, fmaf(c0.z, nz, c0.w))) + qq2;
            float d1 = fmaf(c1.x, nx, fmaf(c1.y, ny, fmaf(c1.z, nz, c1.w))) + qq2;
            float d2 = fmaf(c2.x, nx, fmaf(c2.y, ny, fmaf(c2.z, nz, c2.w))) + qq2;
            float d3 = fmaf(c3.x, nx, fmaf(c3.y, ny, fmaf(c3.z, nz, c3.w))) + qq2;

            float w0 = ex2f_a(-sqrtf_a(d0));
            float w1 = ex2f_a(-sqrtf_a(d1));
            float w2 = ex2f_a(-sqrtf_a(d2));
            float w3 = ex2f_a(-sqrtf_a(d3));

            S0 += w0; X0 = fmaf(w0, c0.x, X0); Y0 = fmaf(w0, c0.y, Y0); Z0 = fmaf(w0, c0.z, Z0);
            S1 += w1; X1 = fmaf(w1, c1.x, X1); Y1 = fmaf(w1, c1.y, Y1); Z1 = fmaf(w1, c1.z, Z1);
            S2 += w2; X2 = fmaf(w2, c2.x, X2); Y2 = fmaf(w2, c2.y, Y2); Z2 = fmaf(w2, c2.z, Z2);
            S3 += w3; X3 = fmaf(w3, c3.x, X3); Y3 = fmaf(w3, c3.y, Y3); Z3 = fmaf(w3, c3.z, Z3);
        }

        float S  = (S0 + S1) + (S2 + S3);
        float Gx = (X0 + X1) + (X2 + X3);
        float Gy = (Y0 + Y1) + (Y2 + Y3);
        float Gz = (Z0 + Z1) + (Z2 + Z3);

        // finalize: grad = (Gc/S)/L - q_orig; clip to 0.3; empty type -> 0
        float gx = 0.f, gy = 0.f, gz = 0.f;
        if (S > 0.f) {
            float inv = rcpf_a(S) * LN2F;
            gx = fmaf(Gx, inv, -qox);
            gy = fmaf(Gy, inv, -qoy);
            gz = fmaf(Gz, inv, -qoz);
            float m2 = fmaf(gx, gx, fmaf(gy, gy, gz * gz));
            if (m2 > CLIP * CLIP) {
                float sc = CLIP * rsqrtf_a(m2);
                gx *= sc; gy *= sc; gz *= sc;
            }
        }
        outp[t * 3 + 0] = gx; outp[t * 3 + 1] = gy; outp[t * 3 + 2] = gz;
    }
}

extern "C" void kernel_launch(void* const* d_in, const int* in_sizes, int n_in,
                              void* d_out, int out_size)
{
    const float* coords = (const float*)d_in[0];   // [16,128,3] f32
    const int*   types  = (const int*)d_in[1];     // [16,128] int32/int64 (detected on device)
    const float* query  = (const float*)d_in[2];   // [16,8192,3] f32
    float*       out    = (float*)d_out;           // [16,8192,5,3] f32

    dim3 grid(PP / THREADS, BB);   // (32, 16) = 512 blocks x 256 threads
    gnf_kernel<<<grid, THREADS>>>(coords, types, query, out);
}

// round 9
// speedup vs baseline: 1.0101x; 1.0067x over previous
#include <cuda_runtime.h>

// Problem constants (from reference)
#define BB 16
#define AA 128
#define PP 8192
#define TT 5
#define K_LOG2E 1.4426950408889634f   // log2(e); TEMPERATURE = 1.0
#define LN2F    0.6931471805599453f   // 1/log2(e)
#define CLIP    0.3f

#define THREADS 256          // 8 warps/block, 1 query per thread
#define MAXU 84              // max 2-atom units: (128 + 5*3 pad)/2 rounded up

typedef unsigned long long ull;

__device__ __forceinline__ float sqrtf_a(float x) {
    float y; asm("sqrt.approx.ftz.f32 %0, %1;" : "=f"(y) : "f"(x)); return y;
}
__device__ __forceinline__ float rcpf_a(float x) {
    float y; asm("rcp.approx.ftz.f32 %0, %1;" : "=f"(y) : "f"(x)); return y;
}
__device__ __forceinline__ float rsqrtf_a(float x) {
    float y; asm("rsqrt.approx.ftz.f32 %0, %1;" : "=f"(y) : "f"(x)); return y;
}
__device__ __forceinline__ ull f2_pack(float lo, float hi) {
    ull r; asm("mov.b64 %0, {%1, %2};" : "=l"(r) : "f"(lo), "f"(hi)); return r;
}
__device__ __forceinline__ void f2_unpack(float& lo, float& hi, ull v) {
    asm("mov.b64 {%0, %1}, %2;" : "=f"(lo), "=f"(hi) : "l"(v));
}
__device__ __forceinline__ ull f2_add(ull a, ull b) {
    ull d; asm("add.rn.f32x2 %0, %1, %2;" : "=l"(d) : "l"(a), "l"(b)); return d;
}
__device__ __forceinline__ ull f2_fma(ull a, ull b, ull c) {
    ull d; asm("fma.rn.f32x2 %0, %1, %2, %3;" : "=l"(d) : "l"(a), "l"(b), "l"(c)); return d;
}
// pack two f32 into f16x2: first PTX operand -> HIGH half
__device__ __forceinline__ unsigned cvt_f16x2(float hi, float lo) {
    unsigned r; asm("cvt.rn.f16x2.f32 %0, %1, %2;" : "=r"(r) : "f"(hi), "f"(lo)); return r;
}
__device__ __forceinline__ unsigned ex2_f16x2(unsigned x) {
    unsigned r; asm("ex2.approx.f16x2 %0, %1;" : "=r"(r) : "r"(x)); return r;
}
// (lo,hi) f16 halves -> packed f32x2 (lo in low lane)
__device__ __forceinline__ ull widen_f16x2(unsigned w) {
    ull r;
    asm("{\n\t"
        ".reg .f16 h0, h1;\n\t"
        ".reg .f32 f0, f1;\n\t"
        "mov.b32 {h0, h1}, %1;\n\t"
        "cvt.f32.f16 f0, h0;\n\t"
        "cvt.f32.f16 f1, h1;\n\t"
        "mov.b64 %0, {f0, f1};\n\t"
        "}" : "=l"(r) : "r"(w));
    return r;
}

__global__ void __launch_bounds__(THREADS)
gnf_kernel(const float* __restrict__ coords,     // [B, A, 3] f32
           const int*   __restrict__ types_raw,  // [B, A] int32 OR int64 (detected)
           const float* __restrict__ query,      // [B, P, 3] f32
           float*       __restrict__ out)        // [B, P, T, 3] f32
{
    // per 2-atom unit j (atoms 2j, 2j+1), packed lane-wise:
    //   sA[j] = { (x_e, x_o), (y_e, y_o) }
    //   sB[j] = { (z_e, z_o), (w_e, w_o) }   w = |c'|^2, c' = c*log2e
    __shared__ ulonglong2 sA[MAXU];
    __shared__ ulonglong2 sB[MAXU];
    __shared__ int sStart[TT + 1];   // padded starts (atoms), multiples of 4
    __shared__ int sCnt[TT];
    __shared__ int sOffs[TT];

    const int tid = threadIdx.x;
    const int b   = blockIdx.y;

    // ---- sentinel: |c'|^2 = 1e30 -> s = 1e15 -> f16 +inf -> ex2(-inf) = 0; coords 0
    for (int j = tid; j < MAXU; j += THREADS) {
        sA[j].x = 0ULL; sA[j].y = 0ULL;
        sB[j].x = 0ULL; sB[j].y = f2_pack(1e30f, 1e30f);
    }
    if (tid < TT) sCnt[tid] = 0;

    // ---- dtype detection: sample odd words (1 LDG/thread); int64 iff all in {0,-1}
    {
        int w = types_raw[2 * (tid & 255) + 1];
        bool okk = (w == 0) || (w == -1);
        const int is64 = __syncthreads_and(okk ? 1 : 0);   // also fences sentinel fill

        // ---- counting sort by type, segments padded to multiples of 4 atoms
        int t_mine = -1;
        if (tid < AA) {
            long long tv;
            if (is64) tv = ((const long long*)types_raw)[(long)b * AA + tid];
            else      tv = (long long)types_raw[(long)b * AA + tid];
            if (tv >= 0 && tv < TT) {
                t_mine = (int)tv;
                atomicAdd(&sCnt[t_mine], 1);
            }
        }
        __syncthreads();
        if (tid == 0) {
            int s = 0;
            #pragma unroll
            for (int k = 0; k < TT; k++) {
                sStart[k] = s; sOffs[k] = s;
                s += (sCnt[k] + 3) & ~3;
            }
            sStart[TT] = s;
        }
        __syncthreads();
        if (t_mine >= 0) {
            int pos = atomicAdd(&sOffs[t_mine], 1);
            const float* c = coords + ((long)b * AA + tid) * 3;
            float cx = c[0] * K_LOG2E, cy = c[1] * K_LOG2E, cz = c[2] * K_LOG2E;
            float cw = fmaf(cx, cx, fmaf(cy, cy, cz * cz));
            int j = pos >> 1, lane = pos & 1;
            float* fA = (float*)&sA[j];   // [x_e, x_o, y_e, y_o]
            float* fB = (float*)&sB[j];   // [z_e, z_o, w_e, w_o]
            fA[lane]     = cx;
            fA[2 + lane] = cy;
            fB[lane]     = cz;
            fB[2 + lane] = cw;
        }
        __syncthreads();
    }

    // ---- one query per thread
    const int q0 = blockIdx.x * THREADS + tid;
    const float* qp = query + ((long)b * PP + q0) * 3;
    const float qox = qp[0], qoy = qp[1], qoz = qp[2];
    const float nx = qox * (-2.f * K_LOG2E);
    const float ny = qoy * (-2.f * K_LOG2E);
    const float nz = qoz * (-2.f * K_LOG2E);
    const float qq2 = 0.25f * fmaf(nx, nx, fmaf(ny, ny, nz * nz));   // +|q'|^2
    const ull nx2 = f2_pack(nx, nx);
    const ull ny2 = f2_pack(ny, ny);
    const ull nz2 = f2_pack(nz, nz);
    const ull qq22 = f2_pack(qq2, qq2);

    float* outp = out + ((long)b * PP + q0) * (TT * 3);

    #pragma unroll
    for (int t = 0; t < TT; t++) {
        const int us = sStart[t] >> 1;        // unit range, length multiple of 2
        const int ue = sStart[t + 1] >> 1;

        ull Sa = 0ULL, Xa = 0ULL, Ya = 0ULL, Za = 0ULL;   // stream A accums (f32x2)
        ull Sb = 0ULL, Xb = 0ULL, Yb = 0ULL, Zb = 0ULL;   // stream B

        for (int j = us; j < ue; j += 2) {
            const ulonglong2 a0 = sA[j],     b0 = sB[j];
            const ulonglong2 a1 = sA[j + 1], b1 = sB[j + 1];

            // d2 = |c|^2 + |q|^2 - 2 c.q   (packed over the 2 atoms of the unit)
            ull t0 = f2_fma(a0.x, nx2, b0.y);
            ull t1 = f2_fma(a1.x, nx2, b1.y);
            t0 = f2_fma(a0.y, ny2, t0);
            t1 = f2_fma(a1.y, ny2, t1);
            t0 = f2_fma(b0.x, nz2, t0);
            t1 = f2_fma(b1.x, nz2, t1);
            t0 = f2_add(t0, qq22);
            t1 = f2_add(t1, qq22);

            float d00, d01, d10, d11;
            f2_unpack(d00, d01, t0);
            f2_unpack(d10, d11, t1);

            float s00 = sqrtf_a(d00), s01 = sqrtf_a(d01);
            float s10 = sqrtf_a(d10), s11 = sqrtf_a(d11);

            // pack (lo=s_even, hi=s_odd), negate both halves, one MUFU ex2 per unit
            unsigned h0 = cvt_f16x2(s01, s00) ^ 0x80008000u;
            unsigned h1 = cvt_f16x2(s11, s10) ^ 0x80008000u;
            ull w0 = widen_f16x2(ex2_f16x2(h0));   // (w_e, w_o) f32x2
            ull w1 = widen_f16x2(ex2_f16x2(h1));

            Sa = f2_add(Sa, w0);
            Xa = f2_fma(w0, a0.x, Xa);
            Ya = f2_fma(w0, a0.y, Ya);
            Za = f2_fma(w0, b0.x, Za);

            Sb = f2_add(Sb, w1);
            Xb = f2_fma(w1, a1.x, Xb);
            Yb = f2_fma(w1, a1.y, Yb);
            Zb = f2_fma(w1, b1.x, Zb);
        }

        // horizontal reduction over lanes + streams
        float u, v, S, Gx, Gy, Gz;
        f2_unpack(u, v, f2_add(Sa, Sb)); S  = u + v;
        f2_unpack(u, v, f2_add(Xa, Xb)); Gx = u + v;
        f2_unpack(u, v, f2_add(Ya, Yb)); Gy = u + v;
        f2_unpack(u, v, f2_add(Za, Zb)); Gz = u + v;

        // finalize: grad = (Gc/S)/L - q_orig; clip to 0.3; empty type -> 0
        float gx = 0.f, gy = 0.f, gz = 0.f;
        if (S > 0.f) {
            float inv = rcpf_a(S) * LN2F;
            gx = fmaf(Gx, inv, -qox);
            gy = fmaf(Gy, inv, -qoy);
            gz = fmaf(Gz, inv, -qoz);
            float m2 = fmaf(gx, gx, fmaf(gy, gy, gz * gz));
            if (m2 > CLIP * CLIP) {
                float sc = CLIP * rsqrtf_a(m2);
                gx *= sc; gy *= sc; gz *= sc;
            }
        }
        outp[t * 3 + 0] = gx; outp[t * 3 + 1] = gy; outp[t * 3 + 2] = gz;
    }
}

extern "C" void kernel_launch(void* const* d_in, const int* in_sizes, int n_in,
                              void* d_out, int out_size)
{
    const float* coords = (const float*)d_in[0];   // [16,128,3] f32
    const int*   types  = (const int*)d_in[1];     // [16,128] int32/int64 (detected on device)
    const float* query  = (const float*)d_in[2];   // [16,8192,3] f32
    float*       out    = (float*)d_out;           // [16,8192,5,3] f32

    dim3 grid(PP / THREADS, BB);   // (32, 16) = 512 blocks x 256 threads
    gnf_kernel<<<grid, THREADS>>>(coords, types, query, out);
}

// round 10
// speedup vs baseline: 1.0452x; 1.0348x over previous
#include <cuda_runtime.h>
#include <cuda_fp16.h>

// Problem constants (from reference)
#define BB 16
#define AA 128
#define PP 8192
#define TT 5
#define K_LOG2E 1.4426950408889634f   // log2(e); TEMPERATURE = 1.0
#define CLIP    0.3f

#define THREADS 256        // 8 warps/block
#define QPB 128            // queries per block: each warp owns 16 queries
#define NCOL 24            // B columns: 5 types * 4 (S,Gx,Gy,Gz), padded to 24
#define KPAD 136           // padded k-stride (halves) for BT rows: bank-conflict-free

__device__ __forceinline__ float sqrtf_a(float x) {
    float y; asm("sqrt.approx.ftz.f32 %0, %1;" : "=f"(y) : "f"(x)); return y;
}
__device__ __forceinline__ float rcpf_a(float x) {
    float y; asm("rcp.approx.ftz.f32 %0, %1;" : "=f"(y) : "f"(x)); return y;
}
__device__ __forceinline__ float rsqrtf_a(float x) {
    float y; asm("rsqrt.approx.ftz.f32 %0, %1;" : "=f"(y) : "f"(x)); return y;
}
// cvt two f32 -> f16x2; FIRST operand lands in the HIGH half (verified in R9)
__device__ __forceinline__ unsigned cvt_f16x2(float hi, float lo) {
    unsigned r; asm("cvt.rn.f16x2.f32 %0, %1, %2;" : "=r"(r) : "f"(hi), "f"(lo)); return r;
}
__device__ __forceinline__ unsigned ex2_f16x2(unsigned x) {
    unsigned r; asm("ex2.approx.f16x2 %0, %1;" : "=r"(r) : "r"(x)); return r;
}
// D += A(16x16 f16) * B(16x8 f16), f32 accumulate
__device__ __forceinline__ void mma16816(float c[4],
                                         unsigned a0, unsigned a1, unsigned a2, unsigned a3,
                                         unsigned b0, unsigned b1) {
    asm volatile(
        "mma.sync.aligned.m16n8k16.row.col.f32.f16.f16.f32 "
        "{%0,%1,%2,%3}, {%4,%5,%6,%7}, {%8,%9}, {%0,%1,%2,%3};"
        : "+f"(c[0]), "+f"(c[1]), "+f"(c[2]), "+f"(c[3])
        : "r"(a0), "r"(a1), "r"(a2), "r"(a3), "r"(b0), "r"(b1));
}

__global__ void __launch_bounds__(THREADS)
gnf_kernel(const float* __restrict__ coords,     // [B, A, 3] f32
           const int*   __restrict__ types_raw,  // [B, A] int32 OR int64 (detected)
           const float* __restrict__ query,      // [B, P, 3] f32
           float*       __restrict__ out)        // [B, P, T, 3] f32
{
    // sAtom[a] = (cx', cy', cz', |c'|^2), c' = c * log2e  -> for the d^2 dot
    // sBhi/sBlo: B^T [NCOL][KPAD] halves; col 4t+{0,1,2,3} = (1, cx, cy, cz) split-f16
    __shared__ float4 sAtom[AA];
    __shared__ __half sBhi[NCOL * KPAD];
    __shared__ __half sBlo[NCOL * KPAD];

    const int tid = threadIdx.x;
    const int b   = blockIdx.y;

    // ---- zero B matrices (scattered writes below fill only valid slots)
    for (int i = tid; i < NCOL * KPAD / 2; i += THREADS) {
        ((unsigned*)sBhi)[i] = 0u;
        ((unsigned*)sBlo)[i] = 0u;
    }

    // ---- dtype detection: sample odd words (1 LDG/thread); int64 iff all in {0,-1}
    {
        int w = types_raw[2 * (tid & 255) + 1];
        bool okk = (w == 0) || (w == -1);
        const int is64 = __syncthreads_and(okk ? 1 : 0);   // also fences B zero-fill

        // ---- build atom table + B matrix (threads 0..127, one atom each)
        if (tid < AA) {
            long long tv;
            if (is64) tv = ((const long long*)types_raw)[(long)b * AA + tid];
            else      tv = (long long)types_raw[(long)b * AA + tid];
            const float* c = coords + ((long)b * AA + tid) * 3;

            if (tv >= 0 && tv < TT) {
                float rx = c[0], ry = c[1], rz = c[2];       // real coords for B
                float cx = rx * K_LOG2E, cy = ry * K_LOG2E, cz = rz * K_LOG2E;
                sAtom[tid] = make_float4(cx, cy, cz,
                                         fmaf(cx, cx, fmaf(cy, cy, cz * cz)));
                int t4 = (int)tv * 4;
                // col t4+0: ones (S); +1,2,3: coords (hi + lo split)
                sBhi[(t4 + 0) * KPAD + tid] = __float2half_rn(1.f);
                float v[3] = {rx, ry, rz};
                #pragma unroll
                for (int j = 0; j < 3; j++) {
                    __half h = __float2half_rn(v[j]);
                    sBhi[(t4 + 1 + j) * KPAD + tid] = h;
                    sBlo[(t4 + 1 + j) * KPAD + tid] =
                        __float2half_rn(v[j] - __half2float(h));
                }
            } else {
                // invalid atom: B row stays zero; make w underflow to 0 too
                sAtom[tid] = make_float4(0.f, 0.f, 0.f, 1e30f);
            }
        }
        __syncthreads();
    }

    // ---- warp tiling: warp owns 16 queries (rows); lane roles per mma fragment
    const int warp = tid >> 5;
    const int lane = tid & 31;
    const int r    = lane >> 2;        // 0..7   (fragment row group / B col-in-tile)
    const int kq   = (lane & 3) * 2;   // 0,2,4,6 (fragment k pair base)
    const int qb   = blockIdx.x * QPB + warp * 16;

    // query params for rows r and r+8
    const float* qp0 = query + ((long)b * PP + qb + r) * 3;
    const float* qp1 = query + ((long)b * PP + qb + r + 8) * 3;
    const float n0x = qp0[0] * (-2.f * K_LOG2E), n0y = qp0[1] * (-2.f * K_LOG2E),
                n0z = qp0[2] * (-2.f * K_LOG2E);
    const float n1x = qp1[0] * (-2.f * K_LOG2E), n1y = qp1[1] * (-2.f * K_LOG2E),
                n1z = qp1[2] * (-2.f * K_LOG2E);
    const float qq0 = 0.25f * fmaf(n0x, n0x, fmaf(n0y, n0y, n0z * n0z));
    const float qq1 = 0.25f * fmaf(n1x, n1x, fmaf(n1y, n1y, n1z * n1z));

    float acc[3][4];
    #pragma unroll
    for (int nt = 0; nt < 3; nt++)
        #pragma unroll
        for (int j = 0; j < 4; j++) acc[nt][j] = 0.f;

    // ---- main loop: 8 k-tiles of 16 atoms
    #pragma unroll
    for (int kt = 0; kt < 8; kt++) {
        const int k0 = kt * 16 + kq;
        const float4 cA = sAtom[k0];
        const float4 cB = sAtom[k0 + 1];
        const float4 cC = sAtom[k0 + 8];
        const float4 cD = sAtom[k0 + 9];

        // d^2 = |c|^2 + |q|^2 - 2 c.q  (scaled coords) for 2 queries x 4 atoms
        float dA0 = fmaf(cA.x, n0x, fmaf(cA.y, n0y, fmaf(cA.z, n0z, cA.w))) + qq0;
        float dB0 = fmaf(cB.x, n0x, fmaf(cB.y, n0y, fmaf(cB.z, n0z, cB.w))) + qq0;
        float dC0 = fmaf(cC.x, n0x, fmaf(cC.y, n0y, fmaf(cC.z, n0z, cC.w))) + qq0;
        float dD0 = fmaf(cD.x, n0x, fmaf(cD.y, n0y, fmaf(cD.z, n0z, cD.w))) + qq0;
        float dA1 = fmaf(cA.x, n1x, fmaf(cA.y, n1y, fmaf(cA.z, n1z, cA.w))) + qq1;
        float dB1 = fmaf(cB.x, n1x, fmaf(cB.y, n1y, fmaf(cB.z, n1z, cB.w))) + qq1;
        float dC1 = fmaf(cC.x, n1x, fmaf(cC.y, n1y, fmaf(cC.z, n1z, cC.w))) + qq1;
        float dD1 = fmaf(cD.x, n1x, fmaf(cD.y, n1y, fmaf(cD.z, n1z, cD.w))) + qq1;

        // w = 2^(-sqrt(d2)) packed as mma A-fragment regs (lo half = lower k)
        unsigned a0 = ex2_f16x2(cvt_f16x2(sqrtf_a(dB0), sqrtf_a(dA0)) ^ 0x80008000u);
        unsigned a1 = ex2_f16x2(cvt_f16x2(sqrtf_a(dB1), sqrtf_a(dA1)) ^ 0x80008000u);
        unsigned a2 = ex2_f16x2(cvt_f16x2(sqrtf_a(dD0), sqrtf_a(dC0)) ^ 0x80008000u);
        unsigned a3 = ex2_f16x2(cvt_f16x2(sqrtf_a(dD1), sqrtf_a(dC1)) ^ 0x80008000u);

        #pragma unroll
        for (int nt = 0; nt < 3; nt++) {
            const int bbase = (nt * 8 + r) * KPAD + kt * 16 + kq;
            unsigned bh0 = *(const unsigned*)&sBhi[bbase];
            unsigned bh1 = *(const unsigned*)&sBhi[bbase + 8];
            unsigned bl0 = *(const unsigned*)&sBlo[bbase];
            unsigned bl1 = *(const unsigned*)&sBlo[bbase + 8];
            mma16816(acc[nt], a0, a1, a2, a3, bh0, bh1);
            mma16816(acc[nt], a0, a1, a2, a3, bl0, bl1);
        }
    }

    // ---- epilogue: fragments -> (S,Gx,Gy,Gz) per (query,type), finalize, store
    #pragma unroll
    for (int nt = 0; nt < 3; nt++) {
        float c0 = acc[nt][0], c1 = acc[nt][1], c2 = acc[nt][2], c3 = acc[nt][3];
        float x0 = __shfl_xor_sync(0xffffffffu, c0, 1);
        float x1 = __shfl_xor_sync(0xffffffffu, c1, 1);
        float x2 = __shfl_xor_sync(0xffffffffu, c2, 1);
        float x3 = __shfl_xor_sync(0xffffffffu, c3, 1);

        const int t = 2 * nt + ((lane & 3) >> 1);
        if (t < TT) {
            float S, Gx, Gy, Gz;
            int q;
            if ((lane & 1) == 0) { S = c0; Gx = c1; Gy = x0; Gz = x1; q = qb + r; }
            else                 { S = x2; Gx = x3; Gy = c2; Gz = c3; q = qb + r + 8; }

            const float* qp = query + ((long)b * PP + q) * 3;
            float gx = 0.f, gy = 0.f, gz = 0.f;
            if (S > 0.f) {
                float inv = rcpf_a(S);
                gx = fmaf(Gx, inv, -qp[0]);
                gy = fmaf(Gy, inv, -qp[1]);
                gz = fmaf(Gz, inv, -qp[2]);
                float m2 = fmaf(gx, gx, fmaf(gy, gy, gz * gz));
                if (m2 > CLIP * CLIP) {
                    float sc = CLIP * rsqrtf_a(m2);
                    gx *= sc; gy *= sc; gz *= sc;
                }
            }
            float* op = out + (((long)b * PP + q) * TT + t) * 3;
            op[0] = gx; op[1] = gy; op[2] = gz;
        }
    }
}

extern "C" void kernel_launch(void* const* d_in, const int* in_sizes, int n_in,
                              void* d_out, int out_size)
{
    const float* coords = (const float*)d_in[0];   // [16,128,3] f32
    const int*   types  = (const int*)d_in[1];     // [16,128] int32/int64 (detected on device)
    const float* query  = (const float*)d_in[2];   // [16,8192,3] f32
    float*       out    = (float*)d_out;           // [16,8192,5,3] f32

    dim3 grid(PP / QPB, BB);   // (64, 16) = 1024 blocks x 256 threads
    gnf_kernel<<<grid, THREADS>>>(coords, types, query, out);
}